// round 1
// baseline (speedup 1.0000x reference)
#include <cuda_runtime.h>
#include <cstdint>

// ---------------- problem constants ----------------
#define B_    4
#define N_    1024
#define CIN_  256
#define HW_   256         // feature map H = W = 256
#define D_    512
#define IN_   2304        // CIN * 3 * 3
#define ROWS_ 4096        // B * N

// ---------------- device scratch (no allocs allowed) ----------------
__device__ float g_featsT[(size_t)B_ * HW_ * HW_ * CIN_]; // NHWC, 256 MB
__device__ float g_bbox[ROWS_ * 4];
__device__ float g_flat[(size_t)ROWS_ * IN_];              // 37.7 MB
__device__ float g_hidden[(size_t)ROWS_ * D_];             // 8 MB
__device__ float g_lines[(size_t)ROWS_ * D_];              // 8 MB
__device__ float g_outt[(size_t)ROWS_ * D_];               // 8 MB (B,N,D)

// ---------------- f32x2 helpers (packed dual-FMA, sm_103a) ----------------
__device__ __forceinline__ unsigned long long pack2(float x) {
    unsigned long long r;
    asm("mov.b64 %0, {%1, %1};" : "=l"(r) : "f"(x));
    return r;
}
__device__ __forceinline__ void fma2(unsigned long long& d,
                                     unsigned long long a,
                                     unsigned long long b) {
    asm("fma.rn.f32x2 %0, %1, %2, %0;" : "+l"(d) : "l"(a), "l"(b));
}
__device__ __forceinline__ float2 unpack2(unsigned long long v) {
    float2 r;
    asm("mov.b64 {%0, %1}, %2;" : "=f"(r.x), "=f"(r.y) : "l"(v));
    return r;
}

// ---------------- kernel 1: bbox from 4-corner boxes ----------------
__global__ void bbox_kernel(const float* __restrict__ boxes) {
    int n = blockIdx.x * blockDim.x + threadIdx.x;
    if (n >= ROWS_) return;
    const float* p = boxes + (size_t)n * 8;
    float x0 = p[0], y0 = p[1], x1 = p[2], y1 = p[3];
    float x2 = p[4], y2 = p[5], x3 = p[6], y3 = p[7];
    float xmin = fminf(fminf(x0, x1), fminf(x2, x3));
    float ymin = fminf(fminf(y0, y1), fminf(y2, y3));
    float xmax = fmaxf(fmaxf(x0, x1), fmaxf(x2, x3));
    float ymax = fmaxf(fmaxf(y0, y1), fmaxf(y2, y3));
    g_bbox[n * 4 + 0] = xmin;
    g_bbox[n * 4 + 1] = ymin;
    g_bbox[n * 4 + 2] = xmax;
    g_bbox[n * 4 + 3] = ymax;
}

// ---------------- kernel 2: NCHW -> NHWC transpose of feats ----------------
// in:  feats[b][c][p]  (p = y*256+x, 65536)
// out: g_featsT[b][p][c]
__global__ void feat_transpose_kernel(const float* __restrict__ in) {
    __shared__ float tile[32][33];
    int b  = blockIdx.z;
    int p0 = blockIdx.x * 32;
    int c0 = blockIdx.y * 32;
    const float* ib = in + (size_t)b * CIN_ * (HW_ * HW_);
    float* ob = g_featsT + (size_t)b * (HW_ * HW_) * CIN_;
    int tx = threadIdx.x, ty = threadIdx.y;
#pragma unroll
    for (int i = 0; i < 4; i++)
        tile[ty + i * 8][tx] = ib[(size_t)(c0 + ty + i * 8) * (HW_ * HW_) + p0 + tx];
    __syncthreads();
#pragma unroll
    for (int i = 0; i < 4; i++)
        ob[(size_t)(p0 + ty + i * 8) * CIN_ + c0 + tx] = tile[tx][ty + i * 8];
}

// ---------------- kernel 3: ROI align -> g_flat (row n, col c*9+bin) ----------------
__global__ __launch_bounds__(256) void roi_kernel() {
    int n = blockIdx.x;          // 0..4095
    int b = n >> 10;
    int c = threadIdx.x;         // channel 0..255
    const float* fb = g_featsT + (size_t)b * (HW_ * HW_) * CIN_;

    float4 bb = *(const float4*)(g_bbox + n * 4);
    float x1 = bb.x * 0.25f, y1 = bb.y * 0.25f;
    float x2 = bb.z * 0.25f, y2 = bb.w * 0.25f;
    float binw = fmaxf(x2 - x1, 1.0f) * (1.0f / 3.0f);
    float binh = fmaxf(y2 - y1, 1.0f) * (1.0f / 3.0f);

    int   yi0[6], yi1[6], xi0[6], xi1[6];
    float yl[6], yv[6], xl[6], xv[6];
#pragma unroll
    for (int s = 0; s < 6; s++) {
        float g = 0.5f * (float)s + 0.25f;
        float yy = y1 + g * binh;
        yv[s] = (yy > -1.0f && yy < 256.0f) ? 1.0f : 0.0f;
        float yc = fminf(fmaxf(yy, 0.0f), 255.0f);
        int i0 = (int)floorf(yc);
        yi0[s] = i0; yi1[s] = min(i0 + 1, 255); yl[s] = yc - (float)i0;

        float xx = x1 + g * binw;
        xv[s] = (xx > -1.0f && xx < 256.0f) ? 1.0f : 0.0f;
        float xc = fminf(fmaxf(xx, 0.0f), 255.0f);
        int j0 = (int)floorf(xc);
        xi0[s] = j0; xi1[s] = min(j0 + 1, 255); xl[s] = xc - (float)j0;
    }

    float acc[9];
#pragma unroll
    for (int i = 0; i < 9; i++) acc[i] = 0.0f;

#pragma unroll
    for (int sy = 0; sy < 6; sy++) {
        float ly = yl[sy], hy = 1.0f - ly;
        int r0 = yi0[sy] * 256, r1 = yi1[sy] * 256;
#pragma unroll
        for (int sx = 0; sx < 6; sx++) {
            float lx = xl[sx], hx = 1.0f - lx;
            float w = 0.25f * yv[sy] * xv[sx];
            const float* p00 = fb + ((size_t)(r0 + xi0[sx])) * CIN_ + c;
            const float* p01 = fb + ((size_t)(r0 + xi1[sx])) * CIN_ + c;
            const float* p10 = fb + ((size_t)(r1 + xi0[sx])) * CIN_ + c;
            const float* p11 = fb + ((size_t)(r1 + xi1[sx])) * CIN_ + c;
            float v = __ldg(p00) * (hy * hx) + __ldg(p01) * (hy * lx)
                    + __ldg(p10) * (ly * hx) + __ldg(p11) * (ly * lx);
            acc[(sy >> 1) * 3 + (sx >> 1)] += v * w;
        }
    }

    __shared__ float st[IN_];
#pragma unroll
    for (int i = 0; i < 9; i++) st[c * 9 + i] = acc[i];
    __syncthreads();
    float* dst = g_flat + (size_t)n * IN_;
    for (int i = c; i < IN_; i += 256) dst[i] = st[i];
}

// ---------------- kernel 4/5: fp32 GEMM with packed f32x2 FMA ----------------
// MODE 0: g_hidden = relu(g_flat @ W1 + b1), K = 2304
// MODE 1: g_lines  =        g_hidden @ W2 + b2, K = 512
#define BM 128
#define BN 64
#define BK 16

template <int MODE>
__global__ __launch_bounds__(256) void gemm_kernel(const float* __restrict__ Bw,
                                                   const float* __restrict__ bias) {
    constexpr int K = (MODE == 0) ? IN_ : D_;
    const float* A = (MODE == 0) ? g_flat : g_hidden;
    float* C       = (MODE == 0) ? g_hidden : g_lines;
    constexpr int Nn = D_;

    __shared__ float As[BK][BM];
    __shared__ float Bs[BK][BN];

    int tid = threadIdx.x;
    int bm = blockIdx.y * BM;
    int bn = blockIdx.x * BN;
    int tr = tid >> 3;           // 0..31 -> 4 rows each
    int tc = tid & 7;            // 0..7  -> 8 cols each

    unsigned long long acc[4][4];
#pragma unroll
    for (int i = 0; i < 4; i++)
#pragma unroll
        for (int j = 0; j < 4; j++) acc[i][j] = 0ULL;

    int arow = tid >> 1;             // 0..127
    int akq  = (tid & 1) * 8;        // 0 or 8
    int bk   = tid >> 4;             // 0..15
    int bn4  = (tid & 15) * 4;

    const float* Arow = A + (size_t)(bm + arow) * K;

    for (int k0 = 0; k0 < K; k0 += BK) {
        float4 a0 = *(const float4*)(Arow + k0 + akq);
        float4 a1 = *(const float4*)(Arow + k0 + akq + 4);
        float4 bv = *(const float4*)(Bw + (size_t)(k0 + bk) * Nn + bn + bn4);
        As[akq + 0][arow] = a0.x; As[akq + 1][arow] = a0.y;
        As[akq + 2][arow] = a0.z; As[akq + 3][arow] = a0.w;
        As[akq + 4][arow] = a1.x; As[akq + 5][arow] = a1.y;
        As[akq + 6][arow] = a1.z; As[akq + 7][arow] = a1.w;
        *(float4*)&Bs[bk][bn4] = bv;
        __syncthreads();

#pragma unroll
        for (int k = 0; k < BK; k++) {
            float4 av  = *(const float4*)&As[k][tr * 4];
            float4 bv0 = *(const float4*)&Bs[k][tc * 8];
            float4 bv1 = *(const float4*)&Bs[k][tc * 8 + 4];
            union { float4 f; unsigned long long u[2]; } ub0, ub1;
            ub0.f = bv0; ub1.f = bv1;
            unsigned long long a2[4] = {pack2(av.x), pack2(av.y), pack2(av.z), pack2(av.w)};
            unsigned long long b2[4] = {ub0.u[0], ub0.u[1], ub1.u[0], ub1.u[1]};
#pragma unroll
            for (int i = 0; i < 4; i++)
#pragma unroll
                for (int j = 0; j < 4; j++) fma2(acc[i][j], a2[i], b2[j]);
        }
        __syncthreads();
    }

#pragma unroll
    for (int i = 0; i < 4; i++) {
        int row = bm + tr * 4 + i;
#pragma unroll
        for (int j = 0; j < 4; j++) {
            int col = bn + tc * 8 + j * 2;
            float2 v = unpack2(acc[i][j]);
            v.x += bias[col];
            v.y += bias[col + 1];
            if (MODE == 0) { v.x = fmaxf(v.x, 0.0f); v.y = fmaxf(v.y, 0.0f); }
            *(float2*)(C + (size_t)row * Nn + col) = v;
        }
    }
}

// ---------------- kernel 6: pos embed + LN1 + add + LN2 ----------------
__device__ __forceinline__ float2 block_reduce2(float v0, float v1) {
    __shared__ float s0[16], s1[16];
    int lane = threadIdx.x & 31, wid = threadIdx.x >> 5;
    __syncthreads();  // protect smem reuse across consecutive calls
#pragma unroll
    for (int o = 16; o > 0; o >>= 1) {
        v0 += __shfl_down_sync(0xffffffffu, v0, o);
        v1 += __shfl_down_sync(0xffffffffu, v1, o);
    }
    if (lane == 0) { s0[wid] = v0; s1[wid] = v1; }
    __syncthreads();
    if (wid == 0) {
        v0 = (lane < 16) ? s0[lane] : 0.0f;
        v1 = (lane < 16) ? s1[lane] : 0.0f;
#pragma unroll
        for (int o = 8; o > 0; o >>= 1) {
            v0 += __shfl_down_sync(0xffffffffu, v0, o);
            v1 += __shfl_down_sync(0xffffffffu, v1, o);
        }
        if (lane == 0) { s0[0] = v0; s1[0] = v1; }
    }
    __syncthreads();
    return make_float2(s0[0], s1[0]);
}

__global__ __launch_bounds__(512) void posln_kernel(
    const float* __restrict__ img_sizes,
    const float* __restrict__ Wb, const float* __restrict__ bbv,
    const float* __restrict__ g1, const float* __restrict__ be1,
    const float* __restrict__ g2, const float* __restrict__ be2) {
    int n = blockIdx.x;
    int b = n >> 10;
    int d = threadIdx.x;

    float s0 = img_sizes[2 * b], s1 = img_sizes[2 * b + 1];
    float q0 = g_bbox[n * 4 + 0] / s0;
    float q1 = g_bbox[n * 4 + 1] / s1;
    float q2 = g_bbox[n * 4 + 2] / s0;
    float q3 = g_bbox[n * 4 + 3] / s1;

    float p = bbv[d] + q0 * Wb[d] + q1 * Wb[D_ + d] + q2 * Wb[2 * D_ + d] + q3 * Wb[3 * D_ + d];
    float2 r = block_reduce2(p, p * p);
    float mu  = r.x * (1.0f / D_);
    float var = r.y * (1.0f / D_) - mu * mu;
    float pos = (p - mu) * rsqrtf(var + 1e-5f) * g1[d] + be1[d];

    float sf = g_lines[(size_t)n * D_ + d] + pos;
    r = block_reduce2(sf, sf * sf);
    mu  = r.x * (1.0f / D_);
    var = r.y * (1.0f / D_) - mu * mu;
    float o = (sf - mu) * rsqrtf(var + 1e-5f) * g2[d] + be2[d];
    g_outt[(size_t)n * D_ + d] = o;
}

// ---------------- kernel 7: (B,N,D) -> (B,D,N) into d_out ----------------
__global__ void out_transpose_kernel(float* __restrict__ out) {
    __shared__ float tile[32][33];
    int b  = blockIdx.z;
    int n0 = blockIdx.x * 32;
    int d0 = blockIdx.y * 32;
    int tx = threadIdx.x, ty = threadIdx.y;
#pragma unroll
    for (int i = 0; i < 4; i++)
        tile[ty + i * 8][tx] = g_outt[((size_t)(b << 10) + n0 + ty + i * 8) * D_ + d0 + tx];
    __syncthreads();
#pragma unroll
    for (int i = 0; i < 4; i++)
        out[((size_t)b * D_ + d0 + ty + i * 8) * N_ + n0 + tx] = tile[tx][ty + i * 8];
}

// ---------------- kernel 8: masks = 1 ----------------
__global__ void masks_kernel(float* __restrict__ m) {
    int i = blockIdx.x * blockDim.x + threadIdx.x;
    if (i < B_ * N_) m[i] = 1.0f;
}

// ---------------- launch ----------------
extern "C" void kernel_launch(void* const* d_in, const int* in_sizes, int n_in,
                              void* d_out, int out_size) {
    const float* feats     = (const float*)d_in[0];
    const float* boxes     = (const float*)d_in[1];
    const float* img_sizes = (const float*)d_in[2];
    const float* W1 = (const float*)d_in[3];
    const float* b1 = (const float*)d_in[4];
    const float* W2 = (const float*)d_in[5];
    const float* b2 = (const float*)d_in[6];
    const float* Wb = (const float*)d_in[7];
    const float* bb = (const float*)d_in[8];
    const float* g1 = (const float*)d_in[9];
    const float* be1 = (const float*)d_in[10];
    const float* g2 = (const float*)d_in[11];
    const float* be2 = (const float*)d_in[12];
    float* out = (float*)d_out;

    bbox_kernel<<<16, 256>>>(boxes);
    feat_transpose_kernel<<<dim3(2048, 8, 4), dim3(32, 8)>>>(feats);
    roi_kernel<<<ROWS_, 256>>>();
    gemm_kernel<0><<<dim3(D_ / BN, ROWS_ / BM), 256>>>(W1, b1);
    gemm_kernel<1><<<dim3(D_ / BN, ROWS_ / BM), 256>>>(W2, b2);
    posln_kernel<<<ROWS_, 512>>>(img_sizes, Wb, bb, g1, be1, g2, be2);
    out_transpose_kernel<<<dim3(32, 16, 4), dim3(32, 8)>>>(out);
    masks_kernel<<<16, 256>>>(out + (size_t)B_ * D_ * N_);
}

// round 2
// speedup vs baseline: 1.2666x; 1.2666x over previous
#include <cuda_runtime.h>
#include <cstdint>

// ---------------- problem constants ----------------
#define B_    4
#define N_    1024
#define CIN_  256
#define HW_   256         // feature map H = W = 256
#define D_    512
#define IN_   2304        // CIN * 3 * 3
#define ROWS_ 4096        // B * N

// ---------------- device scratch (no allocs allowed) ----------------
__device__ float g_featsT[(size_t)B_ * HW_ * HW_ * CIN_]; // NHWC, 256 MB
__device__ float g_bbox[ROWS_ * 4];
__device__ float g_flat[(size_t)ROWS_ * IN_];              // 37.7 MB
__device__ float g_hidden[(size_t)ROWS_ * D_];             // 8 MB
__device__ float g_lines[(size_t)ROWS_ * D_];              // 8 MB
__device__ float g_outt[(size_t)ROWS_ * D_];               // 8 MB (B,N,D)

// ---------------- f32x2 helpers (packed dual-FMA, sm_103a) ----------------
__device__ __forceinline__ unsigned long long pack2(float x) {
    unsigned long long r;
    asm("mov.b64 %0, {%1, %1};" : "=l"(r) : "f"(x));
    return r;
}
__device__ __forceinline__ void fma2(unsigned long long& d,
                                     unsigned long long a,
                                     unsigned long long b) {
    asm("fma.rn.f32x2 %0, %1, %2, %0;" : "+l"(d) : "l"(a), "l"(b));
}
__device__ __forceinline__ float2 unpack2(unsigned long long v) {
    float2 r;
    asm("mov.b64 {%0, %1}, %2;" : "=f"(r.x), "=f"(r.y) : "l"(v));
    return r;
}

// ---------------- kernel 1: bbox from 4-corner boxes ----------------
__global__ void bbox_kernel(const float* __restrict__ boxes) {
    int n = blockIdx.x * blockDim.x + threadIdx.x;
    if (n >= ROWS_) return;
    const float* p = boxes + (size_t)n * 8;
    float x0 = p[0], y0 = p[1], x1 = p[2], y1 = p[3];
    float x2 = p[4], y2 = p[5], x3 = p[6], y3 = p[7];
    g_bbox[n * 4 + 0] = fminf(fminf(x0, x1), fminf(x2, x3));
    g_bbox[n * 4 + 1] = fminf(fminf(y0, y1), fminf(y2, y3));
    g_bbox[n * 4 + 2] = fmaxf(fmaxf(x0, x1), fmaxf(x2, x3));
    g_bbox[n * 4 + 3] = fmaxf(fmaxf(y0, y1), fmaxf(y2, y3));
}

// ---------------- kernel 2: NCHW -> NHWC transpose of feats ----------------
__global__ void feat_transpose_kernel(const float* __restrict__ in) {
    __shared__ float tile[32][33];
    int b  = blockIdx.z;
    int p0 = blockIdx.x * 32;
    int c0 = blockIdx.y * 32;
    const float* ib = in + (size_t)b * CIN_ * (HW_ * HW_);
    float* ob = g_featsT + (size_t)b * (HW_ * HW_) * CIN_;
    int tx = threadIdx.x, ty = threadIdx.y;
#pragma unroll
    for (int i = 0; i < 4; i++)
        tile[ty + i * 8][tx] = ib[(size_t)(c0 + ty + i * 8) * (HW_ * HW_) + p0 + tx];
    __syncthreads();
#pragma unroll
    for (int i = 0; i < 4; i++)
        ob[(size_t)(p0 + ty + i * 8) * CIN_ + c0 + tx] = tile[tx][ty + i * 8];
}

// ---------------- kernel 3: ROI align -> g_flat ----------------
__global__ __launch_bounds__(256) void roi_kernel() {
    int n = blockIdx.x;          // 0..4095
    int b = n >> 10;
    int c = threadIdx.x;         // channel 0..255
    const float* fb = g_featsT + (size_t)b * (HW_ * HW_) * CIN_;

    float4 bb = *(const float4*)(g_bbox + n * 4);
    float x1 = bb.x * 0.25f, y1 = bb.y * 0.25f;
    float x2 = bb.z * 0.25f, y2 = bb.w * 0.25f;
    float binw = fmaxf(x2 - x1, 1.0f) * (1.0f / 3.0f);
    float binh = fmaxf(y2 - y1, 1.0f) * (1.0f / 3.0f);

    int   yi0[6], yi1[6], xi0[6], xi1[6];
    float yl[6], yv[6], xl[6], xv[6];
#pragma unroll
    for (int s = 0; s < 6; s++) {
        float g = 0.5f * (float)s + 0.25f;
        float yy = y1 + g * binh;
        yv[s] = (yy > -1.0f && yy < 256.0f) ? 1.0f : 0.0f;
        float yc = fminf(fmaxf(yy, 0.0f), 255.0f);
        int i0 = (int)floorf(yc);
        yi0[s] = i0; yi1[s] = min(i0 + 1, 255); yl[s] = yc - (float)i0;

        float xx = x1 + g * binw;
        xv[s] = (xx > -1.0f && xx < 256.0f) ? 1.0f : 0.0f;
        float xc = fminf(fmaxf(xx, 0.0f), 255.0f);
        int j0 = (int)floorf(xc);
        xi0[s] = j0; xi1[s] = min(j0 + 1, 255); xl[s] = xc - (float)j0;
    }

    float acc[9];
#pragma unroll
    for (int i = 0; i < 9; i++) acc[i] = 0.0f;

#pragma unroll
    for (int sy = 0; sy < 6; sy++) {
        float ly = yl[sy], hy = 1.0f - ly;
        int r0 = yi0[sy] * 256, r1 = yi1[sy] * 256;
#pragma unroll
        for (int sx = 0; sx < 6; sx++) {
            float lx = xl[sx], hx = 1.0f - lx;
            float w = 0.25f * yv[sy] * xv[sx];
            const float* p00 = fb + ((size_t)(r0 + xi0[sx])) * CIN_ + c;
            const float* p01 = fb + ((size_t)(r0 + xi1[sx])) * CIN_ + c;
            const float* p10 = fb + ((size_t)(r1 + xi0[sx])) * CIN_ + c;
            const float* p11 = fb + ((size_t)(r1 + xi1[sx])) * CIN_ + c;
            float v = __ldg(p00) * (hy * hx) + __ldg(p01) * (hy * lx)
                    + __ldg(p10) * (ly * hx) + __ldg(p11) * (ly * lx);
            acc[(sy >> 1) * 3 + (sx >> 1)] += v * w;
        }
    }

    __shared__ float st[IN_];
#pragma unroll
    for (int i = 0; i < 9; i++) st[c * 9 + i] = acc[i];
    __syncthreads();
    float* dst = g_flat + (size_t)n * IN_;
    for (int i = c; i < IN_; i += 256) dst[i] = st[i];
}

// ---------------- kernel 4/5: fp32 GEMM, 128x128x16 tiles, 8x8 micro ----
// MODE 0: g_hidden = relu(g_flat @ W1 + b1), K = 2304
// MODE 1: g_lines  =        g_hidden @ W2 + b2, K = 512
#define BM 128
#define BN 128
#define BK 16

template <int MODE>
__global__ __launch_bounds__(256) void gemm_kernel(const float* __restrict__ Bw,
                                                   const float* __restrict__ bias) {
    constexpr int K = (MODE == 0) ? IN_ : D_;
    const float* A = (MODE == 0) ? g_flat : g_hidden;
    float* C       = (MODE == 0) ? g_hidden : g_lines;

    __shared__ float As[2][BK][BM + 4];   // k-major (transposed)
    __shared__ float Bs[2][BK][BN];

    const int tid = threadIdx.x;
    const int bm = blockIdx.y * BM;
    const int bn = blockIdx.x * BN;
    const int ty = tid >> 4;       // 0..15 -> 8 rows
    const int tx = tid & 15;       // 0..15 -> 8 cols

    // global loaders
    const int arow = tid >> 1;           // 0..127
    const int akq  = (tid & 1) * 8;      // 0 or 8
    const int bk   = tid >> 4;           // 0..15
    const int bnq  = (tid & 15) * 8;     // 0..120

    const float* Aptr = A + (size_t)(bm + arow) * K + akq;
    const float* Bptr = Bw + (size_t)bk * D_ + bn + bnq;

    unsigned long long acc[8][4];
#pragma unroll
    for (int i = 0; i < 8; i++)
#pragma unroll
        for (int j = 0; j < 4; j++) acc[i][j] = 0ULL;

    // prefetch tile 0
    float4 pa0 = *(const float4*)(Aptr);
    float4 pa1 = *(const float4*)(Aptr + 4);
    float4 pb0 = *(const float4*)(Bptr);
    float4 pb1 = *(const float4*)(Bptr + 4);

    // store tile 0
    As[0][akq + 0][arow] = pa0.x; As[0][akq + 1][arow] = pa0.y;
    As[0][akq + 2][arow] = pa0.z; As[0][akq + 3][arow] = pa0.w;
    As[0][akq + 4][arow] = pa1.x; As[0][akq + 5][arow] = pa1.y;
    As[0][akq + 6][arow] = pa1.z; As[0][akq + 7][arow] = pa1.w;
    *(float4*)&Bs[0][bk][bnq]     = pb0;
    *(float4*)&Bs[0][bk][bnq + 4] = pb1;
    __syncthreads();

    int buf = 0;
    for (int k0 = 0; k0 < K; k0 += BK) {
        const bool has_next = (k0 + BK < K);
        if (has_next) {
            pa0 = *(const float4*)(Aptr + k0 + BK);
            pa1 = *(const float4*)(Aptr + k0 + BK + 4);
            pb0 = *(const float4*)(Bptr + (size_t)(k0 + BK) * D_);
            pb1 = *(const float4*)(Bptr + (size_t)(k0 + BK) * D_ + 4);
        }

#pragma unroll
        for (int k = 0; k < BK; k++) {
            float4 a0 = *(const float4*)&As[buf][k][ty * 8];
            float4 a1 = *(const float4*)&As[buf][k][ty * 8 + 4];
            float4 b0 = *(const float4*)&Bs[buf][k][tx * 8];
            float4 b1 = *(const float4*)&Bs[buf][k][tx * 8 + 4];
            union { float4 f; unsigned long long u[2]; } ub0, ub1;
            ub0.f = b0; ub1.f = b1;
            unsigned long long bv[4] = {ub0.u[0], ub0.u[1], ub1.u[0], ub1.u[1]};
            unsigned long long av[8] = {pack2(a0.x), pack2(a0.y), pack2(a0.z), pack2(a0.w),
                                        pack2(a1.x), pack2(a1.y), pack2(a1.z), pack2(a1.w)};
#pragma unroll
            for (int i = 0; i < 8; i++)
#pragma unroll
                for (int j = 0; j < 4; j++) fma2(acc[i][j], av[i], bv[j]);
        }

        if (has_next) {
            buf ^= 1;
            As[buf][akq + 0][arow] = pa0.x; As[buf][akq + 1][arow] = pa0.y;
            As[buf][akq + 2][arow] = pa0.z; As[buf][akq + 3][arow] = pa0.w;
            As[buf][akq + 4][arow] = pa1.x; As[buf][akq + 5][arow] = pa1.y;
            As[buf][akq + 6][arow] = pa1.z; As[buf][akq + 7][arow] = pa1.w;
            *(float4*)&Bs[buf][bk][bnq]     = pb0;
            *(float4*)&Bs[buf][bk][bnq + 4] = pb1;
            __syncthreads();
        }
    }

    // epilogue
    const int col0 = bn + tx * 8;
    float bias8[8];
#pragma unroll
    for (int j = 0; j < 8; j++) bias8[j] = bias[col0 + j];

#pragma unroll
    for (int i = 0; i < 8; i++) {
        const int row = bm + ty * 8 + i;
        float o[8];
#pragma unroll
        for (int j = 0; j < 4; j++) {
            float2 v = unpack2(acc[i][j]);
            o[2 * j]     = v.x + bias8[2 * j];
            o[2 * j + 1] = v.y + bias8[2 * j + 1];
        }
        if (MODE == 0) {
#pragma unroll
            for (int j = 0; j < 8; j++) o[j] = fmaxf(o[j], 0.0f);
        }
        float* dst = C + (size_t)row * D_ + col0;
        *(float4*)(dst)     = make_float4(o[0], o[1], o[2], o[3]);
        *(float4*)(dst + 4) = make_float4(o[4], o[5], o[6], o[7]);
    }
}

// ---------------- kernel 6: pos embed + LN1 + add + LN2 ----------------
__device__ __forceinline__ float2 block_reduce2(float v0, float v1) {
    __shared__ float s0[16], s1[16];
    int lane = threadIdx.x & 31, wid = threadIdx.x >> 5;
    __syncthreads();
#pragma unroll
    for (int o = 16; o > 0; o >>= 1) {
        v0 += __shfl_down_sync(0xffffffffu, v0, o);
        v1 += __shfl_down_sync(0xffffffffu, v1, o);
    }
    if (lane == 0) { s0[wid] = v0; s1[wid] = v1; }
    __syncthreads();
    if (wid == 0) {
        v0 = (lane < 16) ? s0[lane] : 0.0f;
        v1 = (lane < 16) ? s1[lane] : 0.0f;
#pragma unroll
        for (int o = 8; o > 0; o >>= 1) {
            v0 += __shfl_down_sync(0xffffffffu, v0, o);
            v1 += __shfl_down_sync(0xffffffffu, v1, o);
        }
        if (lane == 0) { s0[0] = v0; s1[0] = v1; }
    }
    __syncthreads();
    return make_float2(s0[0], s1[0]);
}

__global__ __launch_bounds__(512) void posln_kernel(
    const float* __restrict__ img_sizes,
    const float* __restrict__ Wb, const float* __restrict__ bbv,
    const float* __restrict__ g1, const float* __restrict__ be1,
    const float* __restrict__ g2, const float* __restrict__ be2) {
    int n = blockIdx.x;
    int b = n >> 10;
    int d = threadIdx.x;

    float s0 = img_sizes[2 * b], s1 = img_sizes[2 * b + 1];
    float q0 = g_bbox[n * 4 + 0] / s0;
    float q1 = g_bbox[n * 4 + 1] / s1;
    float q2 = g_bbox[n * 4 + 2] / s0;
    float q3 = g_bbox[n * 4 + 3] / s1;

    float p = bbv[d] + q0 * Wb[d] + q1 * Wb[D_ + d] + q2 * Wb[2 * D_ + d] + q3 * Wb[3 * D_ + d];
    float2 r = block_reduce2(p, p * p);
    float mu  = r.x * (1.0f / D_);
    float var = r.y * (1.0f / D_) - mu * mu;
    float pos = (p - mu) * rsqrtf(var + 1e-5f) * g1[d] + be1[d];

    float sf = g_lines[(size_t)n * D_ + d] + pos;
    r = block_reduce2(sf, sf * sf);
    mu  = r.x * (1.0f / D_);
    var = r.y * (1.0f / D_) - mu * mu;
    float o = (sf - mu) * rsqrtf(var + 1e-5f) * g2[d] + be2[d];
    g_outt[(size_t)n * D_ + d] = o;
}

// ---------------- kernel 7: (B,N,D) -> (B,D,N) into d_out ----------------
__global__ void out_transpose_kernel(float* __restrict__ out) {
    __shared__ float tile[32][33];
    int b  = blockIdx.z;
    int n0 = blockIdx.x * 32;
    int d0 = blockIdx.y * 32;
    int tx = threadIdx.x, ty = threadIdx.y;
#pragma unroll
    for (int i = 0; i < 4; i++)
        tile[ty + i * 8][tx] = g_outt[((size_t)(b << 10) + n0 + ty + i * 8) * D_ + d0 + tx];
    __syncthreads();
#pragma unroll
    for (int i = 0; i < 4; i++)
        out[((size_t)b * D_ + d0 + ty + i * 8) * N_ + n0 + tx] = tile[tx][ty + i * 8];
}

// ---------------- kernel 8: masks = 1 ----------------
__global__ void masks_kernel(float* __restrict__ m) {
    int i = blockIdx.x * blockDim.x + threadIdx.x;
    if (i < B_ * N_) m[i] = 1.0f;
}

// ---------------- launch ----------------
extern "C" void kernel_launch(void* const* d_in, const int* in_sizes, int n_in,
                              void* d_out, int out_size) {
    const float* feats     = (const float*)d_in[0];
    const float* boxes     = (const float*)d_in[1];
    const float* img_sizes = (const float*)d_in[2];
    const float* W1 = (const float*)d_in[3];
    const float* b1 = (const float*)d_in[4];
    const float* W2 = (const float*)d_in[5];
    const float* b2 = (const float*)d_in[6];
    const float* Wb = (const float*)d_in[7];
    const float* bb = (const float*)d_in[8];
    const float* g1 = (const float*)d_in[9];
    const float* be1 = (const float*)d_in[10];
    const float* g2 = (const float*)d_in[11];
    const float* be2 = (const float*)d_in[12];
    float* out = (float*)d_out;

    bbox_kernel<<<16, 256>>>(boxes);
    feat_transpose_kernel<<<dim3(2048, 8, 4), dim3(32, 8)>>>(feats);
    roi_kernel<<<ROWS_, 256>>>();
    gemm_kernel<0><<<dim3(D_ / BN, ROWS_ / BM), 256>>>(W1, b1);
    gemm_kernel<1><<<dim3(D_ / BN, ROWS_ / BM), 256>>>(W2, b2);
    posln_kernel<<<ROWS_, 512>>>(img_sizes, Wb, bb, g1, be1, g2, be2);
    out_transpose_kernel<<<dim3(32, 16, 4), dim3(32, 8)>>>(out);
    masks_kernel<<<16, 256>>>(out + (size_t)B_ * D_ * N_);
}